// round 8
// baseline (speedup 1.0000x reference)
#include <cuda_runtime.h>

#define LEN     262144
#define NFFT    1024
#define STRIDE  256
#define HALF    512
#define CUT     513
#define NFRM    1029
#define NB      32
#define PLANE   16892064     // 32*513*1029
#define TB      4            // frames per block

// DP-accurate tables in global memory (small, L1/L2-hot)
__device__ float2 g_tw[CUT];      // W_1024^j, j=0..512 (untangle)
__device__ float2 g_win2[HALF];   // Hann pairs (2j, 2j+1)
__device__ float2 g_T1[8 * 64];   // [ka][l]  = W_512^{l*ka}
__device__ float2 g_T2[8 * 8];    // [kc][n0] = W_64^{n0*kc}

__global__ void init_tables() {
    int j = blockIdx.x * blockDim.x + threadIdx.x;
    if (j < CUT) {
        double s, c;
        sincospi(-(double)j / 512.0, &s, &c);
        float2 w = make_float2((float)c, (float)s);
        if (j == 512) w = make_float2(-1.0f, 0.0f);  // pin: Xi[512] exactly +0
        if (j == 0)   w = make_float2( 1.0f, 0.0f);
        if (j == 256) w = make_float2( 0.0f, -1.0f);
        g_tw[j] = w;
    }
    if (j < HALF) {
        double s0, c0, s1, c1;
        sincospi(2.0 * (double)(2*j)     / (double)NFFT, &s0, &c0);
        sincospi(2.0 * (double)(2*j + 1) / (double)NFFT, &s1, &c1);
        g_win2[j] = make_float2((float)(0.5 - 0.5*c0), (float)(0.5 - 0.5*c1));
    }
    if (j < 8 * 64) {
        int ka = j >> 6, l = j & 63;
        double s, c;
        sincospi(-(double)(l * ka) / 256.0, &s, &c);   // W_512^{l*ka}
        g_T1[j] = make_float2((float)c, (float)s);
    }
    if (j < 8 * 8) {
        int kc = j >> 3, n0 = j & 7;
        double s, c;
        sincospi(-(double)(n0 * kc) / 32.0, &s, &c);   // W_64^{n0*kc}
        g_T2[j] = make_float2((float)c, (float)s);
    }
}

__device__ __forceinline__ float2 cmul(float2 a, float2 b) {
    return make_float2(fmaf(a.x, b.x, -a.y*b.y), fmaf(a.x, b.y, a.y*b.x));
}
__device__ __forceinline__ float2 cadd(float2 a, float2 b) { return make_float2(a.x+b.x, a.y+b.y); }
__device__ __forceinline__ float2 csub(float2 a, float2 b) { return make_float2(a.x-b.x, a.y-b.y); }

__device__ __forceinline__ void dft8(const float2 a[8], float2 y[8]) {
    float2 e0 = cadd(a[0], a[4]), e1 = csub(a[0], a[4]);
    float2 f0 = cadd(a[2], a[6]), f1 = csub(a[2], a[6]);
    float2 g0 = cadd(a[1], a[5]), g1 = csub(a[1], a[5]);
    float2 h0 = cadd(a[3], a[7]), h1 = csub(a[3], a[7]);
    float2 E0 = cadd(e0, f0), E2 = csub(e0, f0);
    float2 E1 = make_float2(e1.x + f1.y, e1.y - f1.x);
    float2 E3 = make_float2(e1.x - f1.y, e1.y + f1.x);
    float2 O0 = cadd(g0, h0), O2 = csub(g0, h0);
    float2 O1 = make_float2(g1.x + h1.y, g1.y - h1.x);
    float2 O3 = make_float2(g1.x - h1.y, g1.y + h1.x);
    const float C = 0.70710678118654752440f;
    float2 t1 = make_float2(C*(O1.x + O1.y), C*(O1.y - O1.x));
    float2 t2 = make_float2(O2.y, -O2.x);
    float2 t3 = make_float2(C*(O3.y - O3.x), -C*(O3.x + O3.y));
    y[0] = cadd(E0, O0); y[4] = csub(E0, O0);
    y[1] = cadd(E1, t1); y[5] = csub(E1, t1);
    y[2] = cadd(E2, t2); y[6] = csub(E2, t2);
    y[3] = cadd(E3, t3); y[7] = csub(E3, t3);
}

// 256 threads = 4 frames x 64 lanes. Register radix-8^3 FFT.
// Vectorized exchanges (STS.128 / LDS.64), float2 Z + staging.
__global__ __launch_bounds__(256) void stft_kernel(const float* __restrict__ x,
                                                   float* __restrict__ out) {
    __shared__ __align__(16) float2 fbuf[TB][640];   // 4 x 5120 B (exchanges / Z, aliased)
    __shared__ float2 stg[CUT * 5];                  // {mag, ang}, row stride 5 over f

    const int tid = threadIdx.x;
    const int f   = tid >> 6;        // frame within block
    const int l   = tid & 63;        // lane within frame
    const int t0  = blockIdx.x * TB;
    const int b   = blockIdx.y;
    const int t   = t0 + f;

    float2* b2 = fbuf[f];
    const int n0 = l & 7, n1 = l >> 3;

    // ---- Pass 1: load (global->regs, windowed, packed), radix-8 over n2 ----
    const float* xb = x + (size_t)b * LEN;
    const int start = t * STRIDE - NFFT;      // always even
    float2 a[8], y[8];
    #pragma unroll
    for (int j = 0; j < 8; j++) {
        int n  = l + 64 * j;                  // packed complex index
        int i0 = start + 2 * n;
        float2 v = make_float2(0.f, 0.f);
        if (i0 >= 0 && i0 < LEN) v = *(const float2*)(xb + i0);
        float2 w = g_win2[n];
        a[j] = make_float2(v.x * w.x, v.y * w.y);
    }
    dft8(a, y);
    #pragma unroll
    for (int ka = 1; ka < 8; ka++) y[ka] = cmul(y[ka], g_T1[ka * 64 + l]);
    {   // exchange 1: idx = 80*n1 + 10*n0 + ka  (ka contiguous, 16B-aligned)
        float4* w4 = (float4*)(b2 + 80 * n1 + 10 * n0);
        #pragma unroll
        for (int j = 0; j < 4; j++)
            w4[j] = make_float4(y[2*j].x, y[2*j].y, y[2*j+1].x, y[2*j+1].y);
    }
    __syncthreads();

    // ---- Pass 2: thread (n0', ka'), radix-8 over n1 ----
    {
        int n0p = l & 7, kap = l >> 3;
        #pragma unroll
        for (int m = 0; m < 8; m++) a[m] = b2[80 * m + 10 * n0p + kap];
        dft8(a, y);
        #pragma unroll
        for (int kc = 1; kc < 8; kc++) y[kc] = cmul(y[kc], g_T2[kc * 8 + n0p]);
        __syncthreads();   // reads done before aliased overwrite
        // exchange 2: idx = 66*n0 + 8*ka + kc  (kc contiguous, 16B-aligned)
        float4* w4 = (float4*)(b2 + 66 * n0p + 8 * kap);
        #pragma unroll
        for (int j = 0; j < 4; j++)
            w4[j] = make_float4(y[2*j].x, y[2*j].y, y[2*j+1].x, y[2*j+1].y);
    }
    __syncthreads();

    // ---- Pass 3: thread (kc, ka), radix-8 over n0; Z[ka + 8kc + 64kd] ----
    {
        int kc = l & 7, ka = l >> 3;
        #pragma unroll
        for (int m = 0; m < 8; m++) a[m] = b2[66 * m + 8 * ka + kc];
        dft8(a, y);
        __syncthreads();   // reads done before aliased Z write
        #pragma unroll
        for (int kd = 0; kd < 8; kd++) {
            int k  = ka + 8 * kc + 64 * kd;
            b2[k + 2 * (k >> 4)] = y[kd];     // padded float2 layout, conflict-free
        }
    }
    __syncthreads();

    // ---- Real-FFT untangle + mag/angle -> float2 staging ----
    #pragma unroll
    for (int r = 0; r < 9; r++) {
        int k = l + 64 * r;
        if (r == 8) { if (l != 0) break; k = 512; }
        int i1 = k & 511,         z1 = i1 + 2 * (i1 >> 4);
        int i2 = (512 - k) & 511, z2 = i2 + 2 * (i2 >> 4);
        float2 ZA = b2[z1];
        float2 ZBc = b2[z2];
        float Bx = ZBc.x, By = -ZBc.y;        // conj
        float2 w = g_tw[k];
        float sr = ZA.x + Bx, si = ZA.y + By;
        float dr = ZA.x - Bx, di = ZA.y - By;
        float Xr = 0.5f * (sr + fmaf(w.x, di,  w.y * dr));
        float Xi = 0.5f * (si - fmaf(w.x, dr, -w.y * di));
        stg[k * 5 + f] = make_float2(sqrtf(fmaf(Xr, Xr, Xi * Xi)), atan2f(Xi, Xr));
    }
    __syncthreads();

    // ---- Coalesced store: fixed f per thread, k strides 64 per iteration ----
    float* __restrict__ mag_out = out;
    float* __restrict__ ang_out = out + PLANE;
    {
        const int k0 = tid >> 2;
        const int ff = tid & 3;
        const bool tok = (t0 + ff) < NFRM;
        size_t o = ((size_t)(b * CUT + k0)) * NFRM + t0 + ff;
        #pragma unroll
        for (int r = 0; r < 9; r++) {
            int k = k0 + 64 * r;
            if (k < CUT && tok) {
                float2 v = stg[k * 5 + ff];
                mag_out[o] = v.x;
                ang_out[o] = v.y;
            }
            o += (size_t)64 * NFRM;
        }
    }
}

extern "C" void kernel_launch(void* const* d_in, const int* in_sizes, int n_in,
                              void* d_out, int out_size) {
    const float* x = (const float*)d_in[0];   // (32, 1, 262144) fp32
    float* out = (float*)d_out;               // mag plane then angle plane
    init_tables<<<(NFFT + 127) / 128, 128>>>();
    dim3 grid((NFRM + TB - 1) / TB, NB);      // 258 x 32
    stft_kernel<<<grid, 256>>>(x, out);
}

// round 9
// speedup vs baseline: 1.0003x; 1.0003x over previous
#include <cuda_runtime.h>

#define LEN     262144
#define NFFT    1024
#define STRIDE  256
#define HALF    512
#define CUT     513
#define NFRM    1029
#define NB      32
#define PLANE   16892064     // 32*513*1029
#define TB      4            // frames per block

// DP-accurate tables in global memory (small, L1/L2-hot)
__device__ float2 g_tw[CUT];      // W_1024^j, j=0..512 (untangle)
__device__ float2 g_win2[HALF];   // Hann pairs (2j, 2j+1)
__device__ float2 g_T1[8 * 64];   // [ka][l]  = W_512^{l*ka}
__device__ float2 g_T2[8 * 8];    // [kc][n0] = W_64^{n0*kc}

__global__ void init_tables() {
    int j = blockIdx.x * blockDim.x + threadIdx.x;
    if (j < CUT) {
        double s, c;
        sincospi(-(double)j / 512.0, &s, &c);
        float2 w = make_float2((float)c, (float)s);
        if (j == 512) w = make_float2(-1.0f, 0.0f);  // pin: Xi[512] exactly +0
        if (j == 0)   w = make_float2( 1.0f, 0.0f);
        if (j == 256) w = make_float2( 0.0f, -1.0f);
        g_tw[j] = w;
    }
    if (j < HALF) {
        double s0, c0, s1, c1;
        sincospi(2.0 * (double)(2*j)     / (double)NFFT, &s0, &c0);
        sincospi(2.0 * (double)(2*j + 1) / (double)NFFT, &s1, &c1);
        g_win2[j] = make_float2((float)(0.5 - 0.5*c0), (float)(0.5 - 0.5*c1));
    }
    if (j < 8 * 64) {
        int ka = j >> 6, l = j & 63;
        double s, c;
        sincospi(-(double)(l * ka) / 256.0, &s, &c);   // W_512^{l*ka}
        g_T1[j] = make_float2((float)c, (float)s);
    }
    if (j < 8 * 8) {
        int kc = j >> 3, n0 = j & 7;
        double s, c;
        sincospi(-(double)(n0 * kc) / 32.0, &s, &c);   // W_64^{n0*kc}
        g_T2[j] = make_float2((float)c, (float)s);
    }
}

__device__ __forceinline__ float2 cmul(float2 a, float2 b) {
    return make_float2(fmaf(a.x, b.x, -a.y*b.y), fmaf(a.x, b.y, a.y*b.x));
}
__device__ __forceinline__ float2 cadd(float2 a, float2 b) { return make_float2(a.x+b.x, a.y+b.y); }
__device__ __forceinline__ float2 csub(float2 a, float2 b) { return make_float2(a.x-b.x, a.y-b.y); }

// y[r] = sum_j a[j] * W8^{j*r}
__device__ __forceinline__ void dft8(const float2 a[8], float2 y[8]) {
    float2 e0 = cadd(a[0], a[4]), e1 = csub(a[0], a[4]);
    float2 f0 = cadd(a[2], a[6]), f1 = csub(a[2], a[6]);
    float2 g0 = cadd(a[1], a[5]), g1 = csub(a[1], a[5]);
    float2 h0 = cadd(a[3], a[7]), h1 = csub(a[3], a[7]);
    float2 E0 = cadd(e0, f0), E2 = csub(e0, f0);
    float2 E1 = make_float2(e1.x + f1.y, e1.y - f1.x);   // e1 - i*f1
    float2 E3 = make_float2(e1.x - f1.y, e1.y + f1.x);   // e1 + i*f1
    float2 O0 = cadd(g0, h0), O2 = csub(g0, h0);
    float2 O1 = make_float2(g1.x + h1.y, g1.y - h1.x);
    float2 O3 = make_float2(g1.x - h1.y, g1.y + h1.x);
    const float C = 0.70710678118654752440f;
    float2 t1 = make_float2(C*(O1.x + O1.y), C*(O1.y - O1.x));    // W8^1*O1
    float2 t2 = make_float2(O2.y, -O2.x);                          // -i*O2
    float2 t3 = make_float2(C*(O3.y - O3.x), -C*(O3.x + O3.y));   // W8^3*O3
    y[0] = cadd(E0, O0); y[4] = csub(E0, O0);
    y[1] = cadd(E1, t1); y[5] = csub(E1, t1);
    y[2] = cadd(E2, t2); y[6] = csub(E2, t2);
    y[3] = cadd(E3, t3); y[7] = csub(E3, t3);
}

// 256 threads = 4 frames x 64 lanes. Register radix-8^3 FFT, scalar
// conflict-free smem exchanges (R7 layout), float2 staging, cheap store.
__global__ __launch_bounds__(256) void stft_kernel(const float* __restrict__ x,
                                                   float* __restrict__ out) {
    __shared__ float2 tw[CUT];            // 4104 B
    __shared__ float  fbuf[TB][1152];     // 4 x 4608 B (exchanges / Z planes, aliased)
    __shared__ float2 stg[CUT * 5];       // {mag, ang}, row stride 5 over f (20520 B)

    const int tid = threadIdx.x;
    const int f   = tid >> 6;        // frame within block
    const int l   = tid & 63;        // lane within frame
    const int t0  = blockIdx.x * TB;
    const int b   = blockIdx.y;
    const int t   = t0 + f;

    for (int r = tid; r < CUT; r += 256) tw[r] = g_tw[r];

    float*  base = fbuf[f];
    float2* b2   = (float2*)base;

    // ---- Pass 1: load (global->regs, windowed, packed), radix-8 over n2 ----
    const float* xb = x + (size_t)b * LEN;
    const int start = t * STRIDE - NFFT;      // always even
    float2 a[8], y[8];
    #pragma unroll
    for (int j = 0; j < 8; j++) {
        int n  = l + 64 * j;                  // packed complex index
        int i0 = start + 2 * n;
        float2 v = make_float2(0.f, 0.f);
        if (i0 >= 0 && i0 < LEN) v = *(const float2*)(xb + i0);
        float2 w = g_win2[n];
        a[j] = make_float2(v.x * w.x, v.y * w.y);
    }
    dft8(a, y);
    #pragma unroll
    for (int ka = 1; ka < 8; ka++) y[ka] = cmul(y[ka], g_T1[ka * 64 + l]);
    {   // exchange 1 write: idx = 72*n1 + n0 + 8*ka  (conflict-free)
        int n0 = l & 7, n1 = l >> 3;
        #pragma unroll
        for (int ka = 0; ka < 8; ka++) b2[72 * n1 + n0 + 8 * ka] = y[ka];
    }
    __syncthreads();

    // ---- Pass 2: thread (n0, ka), radix-8 over n1 ----
    {
        int n0 = l & 7, ka = l >> 3;
        #pragma unroll
        for (int n1 = 0; n1 < 8; n1++) a[n1] = b2[72 * n1 + n0 + 8 * ka];
        dft8(a, y);
        #pragma unroll
        for (int kc = 1; kc < 8; kc++) y[kc] = cmul(y[kc], g_T2[kc * 8 + n0]);
        __syncthreads();   // reads complete before aliased overwrite
        #pragma unroll
        for (int kc = 0; kc < 8; kc++) b2[65 * n0 + kc + 8 * ka] = y[kc];
    }
    __syncthreads();

    // ---- Pass 3: thread (kc, ka), radix-8 over n0; Z[ka + 8kc + 64kd] ----
    {
        int kc = l & 7, ka = l >> 3;
        #pragma unroll
        for (int n0 = 0; n0 < 8; n0++) a[n0] = b2[65 * n0 + kc + 8 * ka];
        dft8(a, y);
        __syncthreads();   // reads complete before aliased Z write
        float* zre = base;
        float* zim = base + 576;
        #pragma unroll
        for (int kd = 0; kd < 8; kd++) {
            int k  = ka + 8 * kc + 64 * kd;
            int zi = k + 4 * (k >> 5);        // conflict-free scalar layout
            zre[zi] = y[kd].x;
            zim[zi] = y[kd].y;
        }
    }
    __syncthreads();

    // ---- Real-FFT untangle + mag/angle -> float2 staging ----
    {
        const float* zre = base;
        const float* zim = base + 576;
        #pragma unroll
        for (int r = 0; r < 9; r++) {
            int k = l + 64 * r;
            if (r == 8) { if (l != 0) break; k = 512; }
            int i1 = k & 511,         z1 = i1 + 4 * (i1 >> 5);
            int i2 = (512 - k) & 511, z2 = i2 + 4 * (i2 >> 5);
            float Ax = zre[z1], Ay = zim[z1];
            float Bx = zre[z2], By = -zim[z2];
            float2 w = tw[k];
            float sr = Ax + Bx, si = Ay + By;
            float dr = Ax - Bx, di = Ay - By;
            float Xr = 0.5f * (sr + fmaf(w.x, di,  w.y * dr));
            float Xi = 0.5f * (si - fmaf(w.x, dr, -w.y * di));
            stg[k * 5 + f] = make_float2(sqrtf(fmaf(Xr, Xr, Xi * Xi)), atan2f(Xi, Xr));
        }
    }
    __syncthreads();

    // ---- Coalesced store: fixed f per thread, k strides 64 per iteration ----
    float* __restrict__ mag_out = out;
    float* __restrict__ ang_out = out + PLANE;
    {
        const int k0 = tid >> 2;
        const int ff = tid & 3;
        const bool tok = (t0 + ff) < NFRM;
        size_t o = ((size_t)(b * CUT + k0)) * NFRM + t0 + ff;
        #pragma unroll
        for (int r = 0; r < 9; r++) {
            int k = k0 + 64 * r;
            if (k < CUT && tok) {
                float2 v = stg[k * 5 + ff];
                mag_out[o] = v.x;
                ang_out[o] = v.y;
            }
            o += (size_t)64 * NFRM;
        }
    }
}

extern "C" void kernel_launch(void* const* d_in, const int* in_sizes, int n_in,
                              void* d_out, int out_size) {
    const float* x = (const float*)d_in[0];   // (32, 1, 262144) fp32
    float* out = (float*)d_out;               // mag plane then angle plane
    init_tables<<<(NFFT + 127) / 128, 128>>>();
    dim3 grid((NFRM + TB - 1) / TB, NB);      // 258 x 32
    stft_kernel<<<grid, 256>>>(x, out);
}

// round 10
// speedup vs baseline: 1.3968x; 1.3964x over previous
#include <cuda_runtime.h>

#define LEN     262144
#define NFFT    1024
#define STRIDE  256
#define HALF    512
#define CUT     513
#define NFRM    1029
#define NB      32
#define PLANE   16892064     // 32*513*1029
#define TB      4            // frames per block
#define FROW    1160         // fbuf row stride in floats (8-bank offset per frame)

// DP-accurate tables in global memory (small, L1/L2-hot)
__device__ float2 g_tw[CUT];      // W_1024^j, j=0..512 (untangle)
__device__ float2 g_win2[HALF];   // Hann pairs (2j, 2j+1)
__device__ float2 g_T1[8 * 64];   // [ka][l]  = W_512^{l*ka}
__device__ float2 g_T2[8 * 8];    // [kc][n0] = W_64^{n0*kc}

__global__ void init_tables() {
    int j = blockIdx.x * blockDim.x + threadIdx.x;
    if (j < CUT) {
        double s, c;
        sincospi(-(double)j / 512.0, &s, &c);
        float2 w = make_float2((float)c, (float)s);
        if (j == 512) w = make_float2(-1.0f, 0.0f);  // pin: Xi[512] exactly +0
        if (j == 0)   w = make_float2( 1.0f, 0.0f);
        if (j == 256) w = make_float2( 0.0f, -1.0f);
        g_tw[j] = w;
    }
    if (j < HALF) {
        double s0, c0, s1, c1;
        sincospi(2.0 * (double)(2*j)     / (double)NFFT, &s0, &c0);
        sincospi(2.0 * (double)(2*j + 1) / (double)NFFT, &s1, &c1);
        g_win2[j] = make_float2((float)(0.5 - 0.5*c0), (float)(0.5 - 0.5*c1));
    }
    if (j < 8 * 64) {
        int ka = j >> 6, l = j & 63;
        double s, c;
        sincospi(-(double)(l * ka) / 256.0, &s, &c);   // W_512^{l*ka}
        g_T1[j] = make_float2((float)c, (float)s);
    }
    if (j < 8 * 8) {
        int kc = j >> 3, n0 = j & 7;
        double s, c;
        sincospi(-(double)(n0 * kc) / 32.0, &s, &c);   // W_64^{n0*kc}
        g_T2[j] = make_float2((float)c, (float)s);
    }
}

__device__ __forceinline__ float2 cmul(float2 a, float2 b) {
    return make_float2(fmaf(a.x, b.x, -a.y*b.y), fmaf(a.x, b.y, a.y*b.x));
}
__device__ __forceinline__ float2 cadd(float2 a, float2 b) { return make_float2(a.x+b.x, a.y+b.y); }
__device__ __forceinline__ float2 csub(float2 a, float2 b) { return make_float2(a.x-b.x, a.y-b.y); }

// y[r] = sum_j a[j] * W8^{j*r}
__device__ __forceinline__ void dft8(const float2 a[8], float2 y[8]) {
    float2 e0 = cadd(a[0], a[4]), e1 = csub(a[0], a[4]);
    float2 f0 = cadd(a[2], a[6]), f1 = csub(a[2], a[6]);
    float2 g0 = cadd(a[1], a[5]), g1 = csub(a[1], a[5]);
    float2 h0 = cadd(a[3], a[7]), h1 = csub(a[3], a[7]);
    float2 E0 = cadd(e0, f0), E2 = csub(e0, f0);
    float2 E1 = make_float2(e1.x + f1.y, e1.y - f1.x);   // e1 - i*f1
    float2 E3 = make_float2(e1.x - f1.y, e1.y + f1.x);   // e1 + i*f1
    float2 O0 = cadd(g0, h0), O2 = csub(g0, h0);
    float2 O1 = make_float2(g1.x + h1.y, g1.y - h1.x);
    float2 O3 = make_float2(g1.x - h1.y, g1.y + h1.x);
    const float C = 0.70710678118654752440f;
    float2 t1 = make_float2(C*(O1.x + O1.y), C*(O1.y - O1.x));    // W8^1*O1
    float2 t2 = make_float2(O2.y, -O2.x);                          // -i*O2
    float2 t3 = make_float2(C*(O3.y - O3.x), -C*(O3.x + O3.y));   // W8^3*O3
    y[0] = cadd(E0, O0); y[4] = csub(E0, O0);
    y[1] = cadd(E1, t1); y[5] = csub(E1, t1);
    y[2] = cadd(E2, t2); y[6] = csub(E2, t2);
    y[3] = cadd(E3, t3); y[7] = csub(E3, t3);
}

// 256 threads = 4 frames x 64 lanes. Register radix-8^3 FFT, scalar
// conflict-free smem exchanges (R7 layout). No staging: untangle is fused
// into the store phase, reading Z directly from all 4 frame buffers.
__global__ __launch_bounds__(256) void stft_kernel(const float* __restrict__ x,
                                                   float* __restrict__ out) {
    __shared__ float2 tw[CUT];            // 4104 B
    __shared__ float  fbuf[TB][FROW];     // 4 x 4640 B (exchanges / Z planes, aliased)

    const int tid = threadIdx.x;
    const int f   = tid >> 6;        // frame within block
    const int l   = tid & 63;        // lane within frame
    const int t0  = blockIdx.x * TB;
    const int b   = blockIdx.y;
    const int t   = t0 + f;

    for (int r = tid; r < CUT; r += 256) tw[r] = g_tw[r];

    float*  base = fbuf[f];
    float2* b2   = (float2*)base;

    // ---- Pass 1: load (global->regs, windowed, packed), radix-8 over n2 ----
    const float* xb = x + (size_t)b * LEN;
    const int start = t * STRIDE - NFFT;      // always even
    float2 a[8], y[8];
    #pragma unroll
    for (int j = 0; j < 8; j++) {
        int n  = l + 64 * j;                  // packed complex index
        int i0 = start + 2 * n;
        float2 v = make_float2(0.f, 0.f);
        if (i0 >= 0 && i0 < LEN) v = *(const float2*)(xb + i0);
        float2 w = g_win2[n];
        a[j] = make_float2(v.x * w.x, v.y * w.y);
    }
    dft8(a, y);
    #pragma unroll
    for (int ka = 1; ka < 8; ka++) y[ka] = cmul(y[ka], g_T1[ka * 64 + l]);
    {   // exchange 1 write: idx = 72*n1 + n0 + 8*ka  (conflict-free)
        int n0 = l & 7, n1 = l >> 3;
        #pragma unroll
        for (int ka = 0; ka < 8; ka++) b2[72 * n1 + n0 + 8 * ka] = y[ka];
    }
    __syncthreads();

    // ---- Pass 2: thread (n0, ka), radix-8 over n1 ----
    {
        int n0 = l & 7, ka = l >> 3;
        #pragma unroll
        for (int n1 = 0; n1 < 8; n1++) a[n1] = b2[72 * n1 + n0 + 8 * ka];
        dft8(a, y);
        #pragma unroll
        for (int kc = 1; kc < 8; kc++) y[kc] = cmul(y[kc], g_T2[kc * 8 + n0]);
        __syncthreads();   // reads complete before aliased overwrite
        #pragma unroll
        for (int kc = 0; kc < 8; kc++) b2[65 * n0 + kc + 8 * ka] = y[kc];
    }
    __syncthreads();

    // ---- Pass 3: thread (kc, ka), radix-8 over n0; Z[ka + 8kc + 64kd] ----
    {
        int kc = l & 7, ka = l >> 3;
        #pragma unroll
        for (int n0 = 0; n0 < 8; n0++) a[n0] = b2[65 * n0 + kc + 8 * ka];
        dft8(a, y);
        __syncthreads();   // reads complete before aliased Z write
        float* zre = base;
        float* zim = base + 576;
        #pragma unroll
        for (int kd = 0; kd < 8; kd++) {
            int k  = ka + 8 * kc + 64 * kd;
            int zi = k + 4 * (k >> 5);        // conflict-free scalar layout
            zre[zi] = y[kd].x;
            zim[zi] = y[kd].y;
        }
    }
    __syncthreads();

    // ---- Fused untangle + mag/angle + store ----
    // Thread (k0 = tid>>2, ff = tid&3): k = k0 + 64*r, frame ff.
    // Reads Z from fbuf[ff] (row stride 1160 -> 8-bank skew per frame:
    // bank = (8*ff + z) % 32, all 32 lane combos distinct, conflict-free).
    // Stores: 4 contiguous t per k across the 4 ff lanes (16B/sector).
    {
        float* __restrict__ mag_out = out;
        float* __restrict__ ang_out = out + PLANE;
        const int k0 = tid >> 2;
        const int ff = tid & 3;
        const bool tok = (t0 + ff) < NFRM;
        const float* zre = fbuf[ff];
        const float* zim = fbuf[ff] + 576;
        size_t o = ((size_t)(b * CUT + k0)) * NFRM + t0 + ff;
        #pragma unroll
        for (int r = 0; r < 9; r++) {
            int k = k0 + 64 * r;
            if (k < CUT && tok) {
                int i1 = k & 511,         z1 = i1 + 4 * (i1 >> 5);
                int i2 = (512 - k) & 511, z2 = i2 + 4 * (i2 >> 5);
                float Ax = zre[z1], Ay = zim[z1];
                float Bx = zre[z2], By = -zim[z2];
                float2 w = tw[k];
                float sr = Ax + Bx, si = Ay + By;
                float dr = Ax - Bx, di = Ay - By;
                float Xr = 0.5f * (sr + fmaf(w.x, di,  w.y * dr));
                float Xi = 0.5f * (si - fmaf(w.x, dr, -w.y * di));
                mag_out[o] = sqrtf(fmaf(Xr, Xr, Xi * Xi));
                ang_out[o] = atan2f(Xi, Xr);
            }
            o += (size_t)64 * NFRM;
        }
    }
}

extern "C" void kernel_launch(void* const* d_in, const int* in_sizes, int n_in,
                              void* d_out, int out_size) {
    const float* x = (const float*)d_in[0];   // (32, 1, 262144) fp32
    float* out = (float*)d_out;               // mag plane then angle plane
    init_tables<<<(NFFT + 127) / 128, 128>>>();
    dim3 grid((NFRM + TB - 1) / TB, NB);      // 258 x 32
    stft_kernel<<<grid, 256>>>(x, out);
}